// round 12
// baseline (speedup 1.0000x reference)
#include <cuda_runtime.h>
#include <cfloat>
#include <stdint.h>

// x [64,256,32,32] f32, codebook [1024,256] f32
#define D_DIM   256
#define HW_DIM  1024
#define NPIX    65536
#define KCODE   1024
#define TOT_ELEMS 16777216

typedef unsigned long long u64;

// Scratch (device globals; allocation-free)
__device__ float  g_cn[KCODE];
__device__ float  g_xn[NPIX];
__device__ double g_partial[512];

// ===================== packed f32x2 helpers (sm_100+) =====================
__device__ __forceinline__ u64 fma2(u64 a, u64 b, u64 c) {
    u64 d;
    asm("fma.rn.f32x2 %0, %1, %2, %3;" : "=l"(d) : "l"(a), "l"(b), "l"(c));
    return d;
}
__device__ __forceinline__ u64 dup2(float v) {
    u64 d;
    asm("mov.b64 %0, {%1, %1};" : "=l"(d) : "f"(v));
    return d;
}
__device__ __forceinline__ float lo2(u64 v) {
    float l, h;
    asm("mov.b64 {%0, %1}, %2;" : "=f"(l), "=f"(h) : "l"(v));
    return l;
}
__device__ __forceinline__ float hi2(u64 v) {
    float l, h;
    asm("mov.b64 {%0, %1}, %2;" : "=f"(l), "=f"(h) : "l"(v));
    return h;
}

// B smem column swizzle (round-9 validated): code c at word c + 4*(c>>5);
// 8-lane LDS.128 phases cover all 32 banks. Row pitch 140 words.
#define BPITCH 140
__device__ __forceinline__ int bcol(int c) { return c + 4 * (c >> 5); }

// ---------------------------------------------------------------------------
// norms (scalar-sequential order — bit-exact-validated in round 2)
// ---------------------------------------------------------------------------
__global__ void cnorm_kernel(const float* __restrict__ cb) {
    int k = blockIdx.x * 256 + threadIdx.x;
    const float* row = cb + (size_t)k * D_DIM;
    float s = 0.f;
    for (int d = 0; d < D_DIM; d++) s = __fadd_rn(s, __fmul_rn(row[d], row[d]));
    g_cn[k] = s;
}
__global__ void xnorm_kernel(const float* __restrict__ x) {
    int b = blockIdx.x, t = threadIdx.x;
    const float* xb = x + (size_t)b * D_DIM * HW_DIM + t * 4;
    float sa[4] = {0.f, 0.f, 0.f, 0.f};
    for (int d = 0; d < D_DIM; d++) {
        float4 v = *(const float4*)(xb + (size_t)d * HW_DIM);
        sa[0] = __fadd_rn(sa[0], __fmul_rn(v.x, v.x));
        sa[1] = __fadd_rn(sa[1], __fmul_rn(v.y, v.y));
        sa[2] = __fadd_rn(sa[2], __fmul_rn(v.z, v.z));
        sa[3] = __fadd_rn(sa[3], __fmul_rn(v.w, v.w));
    }
    int p = b * HW_DIM + t * 4;
#pragma unroll
    for (int j = 0; j < 4; j++) g_xn[p + j] = sa[j];
}

// ---------------------------------------------------------------------------
// Main VQ: round-9 FFMA2 GEMM with A stored pre-duplicated ({x,x} u64) in
// smem and read via broadcast LDS.64 — zero MOVs in the dk loop. Each 32-bit
// lane remains the exact single-accumulator d-ascending fused-FMA chain
// (bit-identical to the validated round-2 kernel).
// ---------------------------------------------------------------------------
__global__ __launch_bounds__(256, 2)
void vq_kernel(const float* __restrict__ x,
               const float* __restrict__ cb,
               float* __restrict__ out) {
    __shared__ __align__(16) u64   As2[16][128];    // [dk][px] = {x,x}  16KB
    __shared__ __align__(16) float Bs[16][BPITCH];  // [dk][swizzled code]
    __shared__ float cns[KCODE];
    __shared__ float xns[128];
    __shared__ float bestv[128];
    __shared__ int   besti[128];
    __shared__ double red[256];

    const int t  = threadIdx.x;
    const int tx = t & 15;
    const int ty = t >> 4;
    const int p0   = blockIdx.x * 128;
    const int bimg = p0 >> 10;
    const int hwb  = p0 & 1023;
    const float* xb = x + (size_t)bimg * D_DIM * HW_DIM + hwb;

#pragma unroll
    for (int i = 0; i < 4; i++) cns[t + i * 256] = g_cn[t + i * 256];
    if (t < 128) {
        xns[t] = g_xn[p0 + t];
        bestv[t] = FLT_MAX; besti[t] = 0x7fffffff;
    }
    __syncthreads();

    // loader mappings (round 9)
    const int dkA0 = t >> 5, dkA1 = dkA0 + 8;
    const int ppA  = (t & 31) * 4;
    const int cc0  = t >> 2, cc1 = cc0 + 64;
    const int ds0  = (t & 3) * 4;
    const int col0 = bcol(cc0), col1 = bcol(cc1);
    const int rcol = tx * 8 + 4 * (tx >> 2);

    for (int nc = 0; nc < 8; nc++) {
        const int cbase = nc * 128;

        // acc2[i][jp]: {dot(px_i, c_{2jp}), dot(px_i, c_{2jp+1})}
        u64 acc2[8][4];
#pragma unroll
        for (int i = 0; i < 8; i++)
#pragma unroll
            for (int j = 0; j < 4; j++) acc2[i][j] = 0ull;

        float4 ra0, ra1, rb0, rb1;
        {
            ra0 = *(const float4*)(xb + (size_t)dkA0 * HW_DIM + ppA);
            ra1 = *(const float4*)(xb + (size_t)dkA1 * HW_DIM + ppA);
            rb0 = *(const float4*)(cb + (size_t)(cbase + cc0) * D_DIM + ds0);
            rb1 = *(const float4*)(cb + (size_t)(cbase + cc1) * D_DIM + ds0);
        }

        for (int kc = 0; kc < 16; kc++) {
            __syncthreads();
            // A: store duplicated pairs once per kc (MOVs amortized 16x)
            {
                ulonglong2 w0, w1;
                w0.x = dup2(ra0.x); w0.y = dup2(ra0.y);
                w1.x = dup2(ra0.z); w1.y = dup2(ra0.w);
                *(ulonglong2*)&As2[dkA0][ppA]     = w0;
                *(ulonglong2*)&As2[dkA0][ppA + 2] = w1;
                w0.x = dup2(ra1.x); w0.y = dup2(ra1.y);
                w1.x = dup2(ra1.z); w1.y = dup2(ra1.w);
                *(ulonglong2*)&As2[dkA1][ppA]     = w0;
                *(ulonglong2*)&As2[dkA1][ppA + 2] = w1;
            }
            Bs[ds0 + 0][col0] = rb0.x; Bs[ds0 + 1][col0] = rb0.y;
            Bs[ds0 + 2][col0] = rb0.z; Bs[ds0 + 3][col0] = rb0.w;
            Bs[ds0 + 0][col1] = rb1.x; Bs[ds0 + 1][col1] = rb1.y;
            Bs[ds0 + 2][col1] = rb1.z; Bs[ds0 + 3][col1] = rb1.w;
            __syncthreads();

            if (kc < 15) {
                const int kn = kc + 1;
                ra0 = *(const float4*)(xb + (size_t)(kn * 16 + dkA0) * HW_DIM + ppA);
                ra1 = *(const float4*)(xb + (size_t)(kn * 16 + dkA1) * HW_DIM + ppA);
                rb0 = *(const float4*)(cb + (size_t)(cbase + cc0) * D_DIM + kn * 16 + ds0);
                rb1 = *(const float4*)(cb + (size_t)(cbase + cc1) * D_DIM + kn * 16 + ds0);
            }

#pragma unroll
            for (int dk = 0; dk < 16; dk++) {
                ulonglong2 bq0 = *(const ulonglong2*)&Bs[dk][rcol];     // pairs 0,1
                ulonglong2 bq1 = *(const ulonglong2*)&Bs[dk][rcol + 4]; // pairs 2,3
                u64 bp[4] = {bq0.x, bq0.y, bq1.x, bq1.y};
                const u64* arow = &As2[dk][ty * 8];
#pragma unroll
                for (int i = 0; i < 8; i++) {
                    u64 ad = arow[i];        // broadcast LDS.64, no MOV
#pragma unroll
                    for (int jp = 0; jp < 4; jp++)
                        acc2[i][jp] = fma2(ad, bp[jp], acc2[i][jp]);
                }
            }
        }

        // Epilogue: d2 = fl(fl(xn - 2*dot) + cn); lowest-index ties on rounded
        // values, ascending code order; shfl-reduce across 16-lane tx group.
#pragma unroll
        for (int i = 0; i < 8; i++) {
            const int r = ty * 8 + i;
            const float xn = xns[r];
            float bv = FLT_MAX;
            int   bi = 0x7fffffff;
#pragma unroll
            for (int jp = 0; jp < 4; jp++) {
                const int c0 = cbase + tx * 8 + 2 * jp;
                float vlo = lo2(acc2[i][jp]);
                float vhi = hi2(acc2[i][jp]);
                float d0 = __fadd_rn(__fadd_rn(xn, __fmul_rn(-2.f, vlo)), cns[c0]);
                float d1 = __fadd_rn(__fadd_rn(xn, __fmul_rn(-2.f, vhi)), cns[c0 + 1]);
                if (d0 < bv) { bv = d0; bi = c0; }
                if (d1 < bv) { bv = d1; bi = c0 + 1; }
            }
#pragma unroll
            for (int off = 8; off > 0; off >>= 1) {
                float ov = __shfl_down_sync(0xffffffffu, bv, off, 16);
                int   oi = __shfl_down_sync(0xffffffffu, bi, off, 16);
                if (ov < bv || (ov == bv && oi < bi)) { bv = ov; bi = oi; }
            }
            if (tx == 0) {
                if (bv < bestv[r] || (bv == bestv[r] && bi < besti[r])) {
                    bestv[r] = bv; besti[r] = bi;
                }
            }
        }
    }
    __syncthreads();

    // Output: STE rounding fl(x + fl(q-x)); loss from fl(x-q)^2 in double.
    double lsum = 0.0;
#pragma unroll 4
    for (int m = 0; m < 128; m++) {
        int e  = m * 256 + t;
        int d  = e >> 7;
        int pp = e & 127;
        size_t addr = (size_t)(bimg * D_DIM + d) * HW_DIM + hwb + pp;
        float q  = cb[(size_t)besti[pp] * D_DIM + d];
        float xv = x[addr];
        out[addr] = __fadd_rn(xv, __fsub_rn(q, xv));
        float diff = __fsub_rn(xv, q);
        lsum += (double)__fmul_rn(diff, diff);
    }
    red[t] = lsum;
    __syncthreads();
    for (int s = 128; s > 0; s >>= 1) {
        if (t < s) red[t] += red[t + s];
        __syncthreads();
    }
    if (t == 0) g_partial[blockIdx.x] = red[0];
}

// ---------------------------------------------------------------------------
__global__ void finalize_kernel(float* __restrict__ out, int out_size) {
    __shared__ double red[512];
    int t = threadIdx.x;
    red[t] = g_partial[t];
    __syncthreads();
    for (int s = 256; s > 0; s >>= 1) {
        if (t < s) red[t] += red[t + s];
        __syncthreads();
    }
    if (t == 0) {
        float m = (float)(red[0] / (double)TOT_ELEMS);
        float loss = (float)(1.25 * (double)m);
        for (int i = TOT_ELEMS; i < out_size; i++) out[i] = loss;
    }
}

// ---------------------------------------------------------------------------
extern "C" void kernel_launch(void* const* d_in, const int* in_sizes, int n_in,
                              void* d_out, int out_size) {
    const float* x  = (const float*)d_in[0];
    const float* cb = (const float*)d_in[1];
    float* out = (float*)d_out;

    cnorm_kernel<<<KCODE / 256, 256>>>(cb);
    xnorm_kernel<<<64, 256>>>(x);
    vq_kernel<<<NPIX / 128, 256>>>(x, cb, out);
    finalize_kernel<<<1, 512>>>(out, out_size);
}

// round 13
// speedup vs baseline: 1.2262x; 1.2262x over previous
#include <cuda_runtime.h>
#include <cfloat>
#include <stdint.h>

// x [64,256,32,32] f32, codebook [1024,256] f32
#define D_DIM   256
#define HW_DIM  1024
#define NPIX    65536
#define KCODE   1024
#define TOT_ELEMS 16777216

typedef unsigned long long u64;

// Scratch (device globals; allocation-free)
__device__ float  g_cn[KCODE];
__device__ float  g_xn[NPIX];
__device__ double g_partial[512];

// ===================== packed f32x2 helpers (sm_100+) =====================
__device__ __forceinline__ u64 fma2(u64 a, u64 b, u64 c) {
    u64 d;
    asm("fma.rn.f32x2 %0, %1, %2, %3;" : "=l"(d) : "l"(a), "l"(b), "l"(c));
    return d;
}
__device__ __forceinline__ u64 dup2(float v) {
    u64 d;
    asm("mov.b64 %0, {%1, %1};" : "=l"(d) : "f"(v));
    return d;
}
__device__ __forceinline__ float lo2(u64 v) {
    float l, h;
    asm("mov.b64 {%0, %1}, %2;" : "=f"(l), "=f"(h) : "l"(v));
    return l;
}
__device__ __forceinline__ float hi2(u64 v) {
    float l, h;
    asm("mov.b64 {%0, %1}, %2;" : "=f"(l), "=f"(h) : "l"(v));
    return h;
}

// B smem column swizzle (round-9 validated): code c at word c + 4*(c>>5);
// 8-lane LDS.128 phases cover all 32 banks. Row pitch 140 words.
#define BPITCH 140
__device__ __forceinline__ int bcol(int c) { return c + 4 * (c >> 5); }

// ---------------------------------------------------------------------------
// norms (scalar-sequential order — bit-exact-validated in round 2)
// ---------------------------------------------------------------------------
__global__ void cnorm_kernel(const float* __restrict__ cb) {
    int k = blockIdx.x * 256 + threadIdx.x;
    const float* row = cb + (size_t)k * D_DIM;
    float s = 0.f;
    for (int d = 0; d < D_DIM; d++) s = __fadd_rn(s, __fmul_rn(row[d], row[d]));
    g_cn[k] = s;
}
__global__ void xnorm_kernel(const float* __restrict__ x) {
    int b = blockIdx.x, t = threadIdx.x;
    const float* xb = x + (size_t)b * D_DIM * HW_DIM + t * 4;
    float sa[4] = {0.f, 0.f, 0.f, 0.f};
    for (int d = 0; d < D_DIM; d++) {
        float4 v = *(const float4*)(xb + (size_t)d * HW_DIM);
        sa[0] = __fadd_rn(sa[0], __fmul_rn(v.x, v.x));
        sa[1] = __fadd_rn(sa[1], __fmul_rn(v.y, v.y));
        sa[2] = __fadd_rn(sa[2], __fmul_rn(v.z, v.z));
        sa[3] = __fadd_rn(sa[3], __fmul_rn(v.w, v.w));
    }
    int p = b * HW_DIM + t * 4;
#pragma unroll
    for (int j = 0; j < 4; j++) g_xn[p + j] = sa[j];
}

// ---------------------------------------------------------------------------
// Main VQ: round-9 FFMA2 GEMM core with double-buffered smem (1 barrier per
// k-chunk) and seamless cross-nc prefetch. Each 32-bit lane is the exact
// single-accumulator d-ascending fused-FMA chain (bit-identical to round 2).
// ---------------------------------------------------------------------------
__global__ __launch_bounds__(256, 2)
void vq_kernel(const float* __restrict__ x,
               const float* __restrict__ cb,
               float* __restrict__ out) {
    __shared__ __align__(16) float As[2][16][128];     // 16KB
    __shared__ __align__(16) float Bs[2][16][BPITCH];  // 17.5KB
    __shared__ float cns[KCODE];
    __shared__ float xns[128];
    __shared__ float bestv[128];
    __shared__ int   besti[128];
    __shared__ double red[256];

    const int t  = threadIdx.x;
    const int tx = t & 15;
    const int ty = t >> 4;
    const int p0   = blockIdx.x * 128;
    const int bimg = p0 >> 10;
    const int hwb  = p0 & 1023;
    const float* xb = x + (size_t)bimg * D_DIM * HW_DIM + hwb;

#pragma unroll
    for (int i = 0; i < 4; i++) cns[t + i * 256] = g_cn[t + i * 256];
    if (t < 128) {
        xns[t] = g_xn[p0 + t];
        bestv[t] = FLT_MAX; besti[t] = 0x7fffffff;
    }
    // ordered before first use by the barrier inside iteration 0

    // loader mappings (round 9)
    const int dkA0 = t >> 5, dkA1 = dkA0 + 8;
    const int ppA  = (t & 31) * 4;
    const int cc0  = t >> 2, cc1 = cc0 + 64;
    const int ds0  = (t & 3) * 4;
    const int col0 = bcol(cc0), col1 = bcol(cc1);
    const int rcol = tx * 8 + 4 * (tx >> 2);

    u64 acc2[8][4];
    float4 ra0, ra1, rb0, rb1;
    // prefetch it = 0 (nc=0, kc=0)
    ra0 = *(const float4*)(xb + (size_t)dkA0 * HW_DIM + ppA);
    ra1 = *(const float4*)(xb + (size_t)dkA1 * HW_DIM + ppA);
    rb0 = *(const float4*)(cb + (size_t)cc0 * D_DIM + ds0);
    rb1 = *(const float4*)(cb + (size_t)cc1 * D_DIM + ds0);

    for (int it = 0; it < 128; it++) {
        const int nc = it >> 4, kc = it & 15, buf = it & 1;

        // store prefetched chunk into buffer `buf` (consumed at it-2,
        // protected by the barrier at it-1)
        *(float4*)&As[buf][dkA0][ppA] = ra0;
        *(float4*)&As[buf][dkA1][ppA] = ra1;
        Bs[buf][ds0 + 0][col0] = rb0.x; Bs[buf][ds0 + 1][col0] = rb0.y;
        Bs[buf][ds0 + 2][col0] = rb0.z; Bs[buf][ds0 + 3][col0] = rb0.w;
        Bs[buf][ds0 + 0][col1] = rb1.x; Bs[buf][ds0 + 1][col1] = rb1.y;
        Bs[buf][ds0 + 2][col1] = rb1.z; Bs[buf][ds0 + 3][col1] = rb1.w;
        __syncthreads();   // the ONLY barrier per iteration

        if (it < 127) {    // prefetch it+1 (crosses nc boundaries seamlessly)
            const int kn = (it + 1) & 15, nn = (it + 1) >> 4;
            ra0 = *(const float4*)(xb + (size_t)(kn * 16 + dkA0) * HW_DIM + ppA);
            ra1 = *(const float4*)(xb + (size_t)(kn * 16 + dkA1) * HW_DIM + ppA);
            rb0 = *(const float4*)(cb + (size_t)(nn * 128 + cc0) * D_DIM + kn * 16 + ds0);
            rb1 = *(const float4*)(cb + (size_t)(nn * 128 + cc1) * D_DIM + kn * 16 + ds0);
        }

        if (kc == 0) {
#pragma unroll
            for (int i = 0; i < 8; i++)
#pragma unroll
                for (int j = 0; j < 4; j++) acc2[i][j] = 0ull;
        }

        // round-9 dk loop, reading buffer `buf`
#pragma unroll
        for (int dk = 0; dk < 16; dk++) {
            float4 af0 = *(const float4*)&As[buf][dk][ty * 8];       // broadcast
            float4 af1 = *(const float4*)&As[buf][dk][ty * 8 + 4];
            ulonglong2 bq0 = *(const ulonglong2*)&Bs[buf][dk][rcol];
            ulonglong2 bq1 = *(const ulonglong2*)&Bs[buf][dk][rcol + 4];
            u64 bp[4] = {bq0.x, bq0.y, bq1.x, bq1.y};
            float av[8] = {af0.x, af0.y, af0.z, af0.w,
                           af1.x, af1.y, af1.z, af1.w};
#pragma unroll
            for (int i = 0; i < 8; i++) {
                u64 ad = dup2(av[i]);
#pragma unroll
                for (int jp = 0; jp < 4; jp++)
                    acc2[i][jp] = fma2(ad, bp[jp], acc2[i][jp]);
            }
        }

        if (kc == 15) {
            // Epilogue: d2 = fl(fl(xn - 2*dot) + cn); lowest-index ties on
            // rounded values; shfl-reduce across 16-lane tx group.
            const int cbase = nc * 128;
#pragma unroll
            for (int i = 0; i < 8; i++) {
                const int r = ty * 8 + i;
                const float xn = xns[r];
                float bv = FLT_MAX;
                int   bi = 0x7fffffff;
#pragma unroll
                for (int jp = 0; jp < 4; jp++) {
                    const int c0 = cbase + tx * 8 + 2 * jp;
                    float vlo = lo2(acc2[i][jp]);
                    float vhi = hi2(acc2[i][jp]);
                    float d0 = __fadd_rn(__fadd_rn(xn, __fmul_rn(-2.f, vlo)), cns[c0]);
                    float d1 = __fadd_rn(__fadd_rn(xn, __fmul_rn(-2.f, vhi)), cns[c0 + 1]);
                    if (d0 < bv) { bv = d0; bi = c0; }
                    if (d1 < bv) { bv = d1; bi = c0 + 1; }
                }
#pragma unroll
                for (int off = 8; off > 0; off >>= 1) {
                    float ov = __shfl_down_sync(0xffffffffu, bv, off, 16);
                    int   oi = __shfl_down_sync(0xffffffffu, bi, off, 16);
                    if (ov < bv || (ov == bv && oi < bi)) { bv = ov; bi = oi; }
                }
                if (tx == 0) {
                    if (bv < bestv[r] || (bv == bestv[r] && bi < besti[r])) {
                        bestv[r] = bv; besti[r] = bi;
                    }
                }
            }
        }
    }
    __syncthreads();

    // Output: STE rounding fl(x + fl(q-x)); loss from fl(x-q)^2 in double.
    double lsum = 0.0;
#pragma unroll 4
    for (int m = 0; m < 128; m++) {
        int e  = m * 256 + t;
        int d  = e >> 7;
        int pp = e & 127;
        size_t addr = (size_t)(bimg * D_DIM + d) * HW_DIM + hwb + pp;
        float q  = cb[(size_t)besti[pp] * D_DIM + d];
        float xv = x[addr];
        out[addr] = __fadd_rn(xv, __fsub_rn(q, xv));
        float diff = __fsub_rn(xv, q);
        lsum += (double)__fmul_rn(diff, diff);
    }
    red[t] = lsum;
    __syncthreads();
    for (int s = 128; s > 0; s >>= 1) {
        if (t < s) red[t] += red[t + s];
        __syncthreads();
    }
    if (t == 0) g_partial[blockIdx.x] = red[0];
}

// ---------------------------------------------------------------------------
__global__ void finalize_kernel(float* __restrict__ out, int out_size) {
    __shared__ double red[512];
    int t = threadIdx.x;
    red[t] = g_partial[t];
    __syncthreads();
    for (int s = 256; s > 0; s >>= 1) {
        if (t < s) red[t] += red[t + s];
        __syncthreads();
    }
    if (t == 0) {
        float m = (float)(red[0] / (double)TOT_ELEMS);
        float loss = (float)(1.25 * (double)m);
        for (int i = TOT_ELEMS; i < out_size; i++) out[i] = loss;
    }
}

// ---------------------------------------------------------------------------
extern "C" void kernel_launch(void* const* d_in, const int* in_sizes, int n_in,
                              void* d_out, int out_size) {
    const float* x  = (const float*)d_in[0];
    const float* cb = (const float*)d_in[1];
    float* out = (float*)d_out;

    cnorm_kernel<<<KCODE / 256, 256>>>(cb);
    xnorm_kernel<<<64, 256>>>(x);
    vq_kernel<<<NPIX / 128, 256>>>(x, cb, out);
    finalize_kernel<<<1, 512>>>(out, out_size);
}